// round 10
// baseline (speedup 1.0000x reference)
#include <cuda_runtime.h>
#include <cuda_fp16.h>
#include <math.h>

typedef unsigned int u32;

#define ALPHA   8.3f
#define C_IN    64
#define C_OUT   64
#define H_IN    256
#define W_IN    256
#define H_OUT   254
#define W_OUT   254

#define NTHREADS 128
#define TILES_PER_BATCH (127 * 4)   // 127 p-pairs x 4 q-tiles of 64
#define NTILES   (4 * TILES_PER_BATCH)

#define PIXN     264                 // 4 rows x 66 cols
// ---- smem layout (bytes) ----
#define OFF_BIAS 0                   // 64 f              = 256
#define OFF_D    256                 // 4 x 66 f          = 1056
#define OFF_DW   1312                // 9 x 128 f         = 4608
#define OFF_IMGH 5920                // 32 cpair x 264 u32 = 33792
#define SMEM_TOTAL 39712

__device__ __forceinline__ u32 packh2(float lo, float hi) {
    u32 r;
    asm("cvt.rn.f16x2.f32 %0, %1, %2;" : "=r"(r) : "f"(hi), "f"(lo));
    return r;
}
__device__ __forceinline__ u32 hmul2(u32 a, u32 b) {
    u32 r;
    asm("mul.rn.f16x2 %0, %1, %2;" : "=r"(r) : "r"(a), "r"(b));
    return r;
}

// mma.sync m16n8k16 fp16: D(16x8,f32) += A(16x16,f16) * B(16x8,f16)
#define MMA_F16(d, a0, a1, a2, a3, b0, b1)                                  \
    asm volatile(                                                           \
        "mma.sync.aligned.m16n8k16.row.col.f32.f16.f16.f32 "                \
        "{%0,%1,%2,%3}, {%4,%5,%6,%7}, {%8,%9}, {%0,%1,%2,%3};"             \
        : "+f"((d)[0]), "+f"((d)[1]), "+f"((d)[2]), "+f"((d)[3])            \
        : "r"(a0), "r"(a1), "r"(a2), "r"(a3), "r"(b0), "r"(b1))

// W pre-packed fp16 B-fragments: [kc16(36)][j(4)][lane(32)] uint4.
__device__ __align__(16) uint4 g_wh[36 * 4 * 32];

__global__ void prep_w(const float* __restrict__ w) {
    int idx = blockIdx.x * blockDim.x + threadIdx.x;
    if (idx >= 36 * 4 * 32) return;
    int lane = idx & 31;
    int j    = (idx >> 5) & 3;
    int kc16 = idx >> 7;
    int kl = kc16 >> 2, cq = kc16 & 3;
    int g = lane >> 2, t = lane & 3;
    int c0 = cq * 16 + 2 * t;
    int oce = (2 * j) * 8 + g;
    int oco = oce + 8;
    uint4 v;
    v.x = packh2(w[(oce * C_IN + c0)     * 9 + kl], w[(oce * C_IN + c0 + 1) * 9 + kl]);
    v.y = packh2(w[(oce * C_IN + c0 + 8) * 9 + kl], w[(oce * C_IN + c0 + 9) * 9 + kl]);
    v.z = packh2(w[(oco * C_IN + c0)     * 9 + kl], w[(oco * C_IN + c0 + 1) * 9 + kl]);
    v.w = packh2(w[(oco * C_IN + c0 + 8) * 9 + kl], w[(oco * C_IN + c0 + 9) * 9 + kl]);
    g_wh[idx] = v;
}

// MMA burst for one cq against 8 nb blocks (mb 0 and 1)
#define MMA_BURST(A, B0, B1, B2, B3)                                        \
    do {                                                                    \
        MMA_F16(acc[0][0], (A)[0], (A)[1], (A)[2], (A)[3], (B0).x, (B0).y); \
        MMA_F16(acc[1][0], (A)[4], (A)[5], (A)[6], (A)[7], (B0).x, (B0).y); \
        MMA_F16(acc[0][1], (A)[0], (A)[1], (A)[2], (A)[3], (B0).z, (B0).w); \
        MMA_F16(acc[1][1], (A)[4], (A)[5], (A)[6], (A)[7], (B0).z, (B0).w); \
        MMA_F16(acc[0][2], (A)[0], (A)[1], (A)[2], (A)[3], (B1).x, (B1).y); \
        MMA_F16(acc[1][2], (A)[4], (A)[5], (A)[6], (A)[7], (B1).x, (B1).y); \
        MMA_F16(acc[0][3], (A)[0], (A)[1], (A)[2], (A)[3], (B1).z, (B1).w); \
        MMA_F16(acc[1][3], (A)[4], (A)[5], (A)[6], (A)[7], (B1).z, (B1).w); \
        MMA_F16(acc[0][4], (A)[0], (A)[1], (A)[2], (A)[3], (B2).x, (B2).y); \
        MMA_F16(acc[1][4], (A)[4], (A)[5], (A)[6], (A)[7], (B2).x, (B2).y); \
        MMA_F16(acc[0][5], (A)[0], (A)[1], (A)[2], (A)[3], (B2).z, (B2).w); \
        MMA_F16(acc[1][5], (A)[4], (A)[5], (A)[6], (A)[7], (B2).z, (B2).w); \
        MMA_F16(acc[0][6], (A)[0], (A)[1], (A)[2], (A)[3], (B3).x, (B3).y); \
        MMA_F16(acc[1][6], (A)[4], (A)[5], (A)[6], (A)[7], (B3).x, (B3).y); \
        MMA_F16(acc[0][7], (A)[0], (A)[1], (A)[2], (A)[3], (B3).z, (B3).w); \
        MMA_F16(acc[1][7], (A)[4], (A)[5], (A)[6], (A)[7], (B3).z, (B3).w); \
    } while (0)

#define LDS_A(dst, cq)                                                      \
    do {                                                                    \
        const u32* pc  = s_imgh + ((cq) * 8 + t) * PIXN + pixbase;          \
        const u32* pc4 = pc + 4 * PIXN;                                     \
        (dst)[0] = pc [g];      (dst)[1] = pc [g + 8];                      \
        (dst)[2] = pc4[g];      (dst)[3] = pc4[g + 8];                      \
        (dst)[4] = pc [16 + g]; (dst)[5] = pc [16 + g + 8];                 \
        (dst)[6] = pc4[16 + g]; (dst)[7] = pc4[16 + g + 8];                 \
    } while (0)

#define BUILD_A(a, e0, e1)                                                  \
    do {                                                                    \
        (a)[0] = hmul2((a)[0], e0); (a)[1] = hmul2((a)[1], e1);             \
        (a)[2] = hmul2((a)[2], e0); (a)[3] = hmul2((a)[3], e1);             \
        (a)[4] = hmul2((a)[4], dwh10); (a)[5] = hmul2((a)[5], dwh11);       \
        (a)[6] = hmul2((a)[6], dwh10); (a)[7] = hmul2((a)[7], dwh11);       \
    } while (0)

__global__ __launch_bounds__(NTHREADS, 3)
void depthconv_mma(const float* __restrict__ img,
                   const float* __restrict__ depth,
                   const float* __restrict__ bias,
                   float* __restrict__ out) {
    extern __shared__ char smem[];
    float* s_b    = (float*)(smem + OFF_BIAS);
    float* s_d    = (float*)(smem + OFF_D);
    float* s_dw   = (float*)(smem + OFF_DW);
    u32*   s_imgh = (u32*)  (smem + OFF_IMGH);   // [cpair(32)][pix(264)]

    const int tid  = threadIdx.x;
    const int lane = tid & 31;
    const int wid  = tid >> 5;          // 4 warps: each 32 M-pixels x 64 oc
    const int g    = lane >> 2;
    const int t    = lane & 3;
    const int pr   = wid >> 1;
    const int qb0  = (wid & 1) * 32;

    const int tIdx = blockIdx.x;
    const int b  = tIdx / TILES_PER_BATCH;
    const int r  = tIdx - b * TILES_PER_BATCH;
    const int p0 = (r >> 2) << 1;
    const int q0 = (r & 3) << 6;
    const int qcnt = min(64, W_OUT - q0);

    if (tid < C_OUT) s_b[tid] = bias[tid];
    for (int i = tid; i < 264; i += NTHREADS) {
        int rr = i / 66, cc = i - rr * 66;
        s_d[i] = depth[(size_t)b * H_IN * W_IN + (p0 + rr) * W_IN +
                       min(q0 + cc, W_IN - 1)];
    }
    {
        const float* ip = img + (size_t)b * C_IN * H_IN * W_IN;
        for (int i = tid; i < 32 * PIXN; i += NTHREADS) {
            int cp  = i / PIXN;
            int pix = i - cp * PIXN;
            int rr  = pix / 66, cc = pix - rr * 66;
            size_t go = ((size_t)(2 * cp) * H_IN + (p0 + rr)) * W_IN +
                        min(q0 + cc, W_IN - 1);
            s_imgh[cp * PIXN + pix] = packh2(ip[go], ip[go + (size_t)H_IN * W_IN]);
        }
    }
    __syncthreads();
    for (int i = tid; i < 1152; i += NTHREADS) {
        int kl = i >> 7, m = i & 127;
        int mpr = m >> 6, qq = m & 63;
        int k = kl / 3, l = kl - k * 3;
        float cen = s_d[(mpr + 1) * 66 + qq + 1];
        s_dw[i] = __expf(-ALPHA * fabsf(s_d[(mpr + k) * 66 + qq + l] - cen));
    }
    __syncthreads();

    float acc[2][8][4];
#pragma unroll
    for (int mb = 0; mb < 2; mb++)
#pragma unroll
        for (int nb = 0; nb < 8; nb++)
#pragma unroll
            for (int rr = 0; rr < 4; rr++) acc[mb][nb][rr] = 0.f;

    // ---- K loop: per-kl batched loads, MMAs cover later loads' latency ----
    const uint4* wlane = g_wh + lane;
    for (int k = 0; k < 3; k++) {
#pragma unroll 1
        for (int l = 0; l < 3; l++) {
            const int kl = k * 3 + l;
            const float* dwp = s_dw + kl * 128 + pr * 64 + qb0;
            const u32 dwh00 = packh2(dwp[g],          dwp[g]);
            const u32 dwh01 = packh2(dwp[g + 8],      dwp[g + 8]);
            const u32 dwh10 = packh2(dwp[16 + g],     dwp[16 + g]);
            const u32 dwh11 = packh2(dwp[16 + g + 8], dwp[16 + g + 8]);
            const int pixbase = (pr + k) * 66 + l + qb0;
            const uint4* wf = wlane + (size_t)(kl * 4) * 128;

            // stage 1: A raw for cq0,cq1 + B for cq0,cq1
            u32 a0[8], a1[8];
            LDS_A(a0, 0);
            LDS_A(a1, 1);
            uint4 b00 = __ldg(wf);       uint4 b01 = __ldg(wf + 32);
            uint4 b02 = __ldg(wf + 64);  uint4 b03 = __ldg(wf + 96);
            uint4 b10 = __ldg(wf + 128); uint4 b11 = __ldg(wf + 160);
            uint4 b12 = __ldg(wf + 192); uint4 b13 = __ldg(wf + 224);

            BUILD_A(a0, dwh00, dwh01);
            BUILD_A(a1, dwh00, dwh01);

            // stage 2: issue B for cq2,cq3 before the first MMA burst
            uint4 b20 = __ldg(wf + 256); uint4 b21 = __ldg(wf + 288);
            uint4 b22 = __ldg(wf + 320); uint4 b23 = __ldg(wf + 352);

            MMA_BURST(a0, b00, b01, b02, b03);

            // stage 3: A raw for cq2,cq3 under cq1's MMAs
            u32 a2[8], a3[8];
            LDS_A(a2, 2);
            LDS_A(a3, 3);

            MMA_BURST(a1, b10, b11, b12, b13);

            uint4 b30 = __ldg(wf + 384); uint4 b31 = __ldg(wf + 416);
            uint4 b32 = __ldg(wf + 448); uint4 b33 = __ldg(wf + 480);

            BUILD_A(a2, dwh00, dwh01);
            BUILD_A(a3, dwh00, dwh01);

            MMA_BURST(a2, b20, b21, b22, b23);
            MMA_BURST(a3, b30, b31, b32, b33);
        }
    }

    // ---- epilogue: bias + store ----
#pragma unroll
    for (int mb = 0; mb < 2; mb++) {
        const int qq0 = qb0 + mb * 16 + g;
#pragma unroll
        for (int nb = 0; nb < 8; nb++) {
            const int oc = nb * 8 + t * 2;
            const float bs0 = s_b[oc], bs1 = s_b[oc + 1];
            const size_t base =
                (((size_t)b * C_OUT + oc) * H_OUT + (p0 + pr)) * W_OUT + q0;
            if (qq0 < qcnt) {
                out[base + qq0]                          = acc[mb][nb][0] + bs0;
                out[base + (size_t)H_OUT * W_OUT + qq0]  = acc[mb][nb][1] + bs1;
            }
            if (qq0 + 8 < qcnt) {
                out[base + qq0 + 8]                         = acc[mb][nb][2] + bs0;
                out[base + (size_t)H_OUT * W_OUT + qq0 + 8] = acc[mb][nb][3] + bs1;
            }
        }
    }
}

extern "C" void kernel_launch(void* const* d_in, const int* in_sizes, int n_in,
                              void* d_out, int out_size) {
    const float* img    = nullptr;
    const float* depth  = nullptr;
    const float* weight = nullptr;
    const float* bias   = nullptr;

    for (int i = 0; i < n_in; i++) {
        switch (in_sizes[i]) {
            case 4 * C_IN * H_IN * W_IN: img    = (const float*)d_in[i]; break;
            case 4 * 1 * H_IN * W_IN:    depth  = (const float*)d_in[i]; break;
            case C_OUT * C_IN * 9:       weight = (const float*)d_in[i]; break;
            case C_OUT:                  bias   = (const float*)d_in[i]; break;
            default: break;
        }
    }

    cudaFuncSetAttribute(depthconv_mma,
                         cudaFuncAttributeMaxDynamicSharedMemorySize, SMEM_TOTAL);

    prep_w<<<(36 * 4 * 32 + 255) / 256, 256>>>(weight);
    depthconv_mma<<<NTILES, NTHREADS, SMEM_TOTAL>>>(img, depth, bias, (float*)d_out);
}

// round 11
// speedup vs baseline: 1.1823x; 1.1823x over previous
#include <cuda_runtime.h>
#include <cuda_fp16.h>
#include <math.h>

typedef unsigned int u32;

#define ALPHA   8.3f
#define C_IN    64
#define C_OUT   64
#define H_IN    256
#define W_IN    256
#define H_OUT   254
#define W_OUT   254

#define NTHREADS 256
#define TILES_PER_BATCH (127 * 4)   // 127 p-pairs x 4 q-tiles of 64
#define NTILES   (4 * TILES_PER_BATCH)

#define PIXN     264                 // 4 rows x 66 cols
// ---- smem layout (bytes) ----
#define OFF_BIAS 0                   // 64 f               = 256
#define OFF_D    256                 // 4 x 66 f           = 1056
#define OFF_DW   1312                // 9 x 128 f          = 4608
#define OFF_IMGH 5920                // 32 cpair x 264 u32 = 33792
#define SMEM_TOTAL 39712

__device__ __forceinline__ u32 packh2(float lo, float hi) {
    u32 r;
    asm("cvt.rn.f16x2.f32 %0, %1, %2;" : "=r"(r) : "f"(hi), "f"(lo));
    return r;
}
__device__ __forceinline__ u32 hmul2(u32 a, u32 b) {
    u32 r;
    asm("mul.rn.f16x2 %0, %1, %2;" : "=r"(r) : "r"(a), "r"(b));
    return r;
}

// mma.sync m16n8k16 fp16: D(16x8,f32) += A(16x16,f16) * B(16x8,f16)
#define MMA_F16(d, a0, a1, a2, a3, b0, b1)                                  \
    asm volatile(                                                           \
        "mma.sync.aligned.m16n8k16.row.col.f32.f16.f16.f32 "                \
        "{%0,%1,%2,%3}, {%4,%5,%6,%7}, {%8,%9}, {%0,%1,%2,%3};"             \
        : "+f"((d)[0]), "+f"((d)[1]), "+f"((d)[2]), "+f"((d)[3])            \
        : "r"(a0), "r"(a1), "r"(a2), "r"(a3), "r"(b0), "r"(b1))

// W pre-packed fp16 B-fragments: [kc16(36)][j(4)][lane(32)] uint4.
// kc16 = kl*4 + cq. For nb pair (2j, 2j+1):
//   .x/.y = b0/b1 of nb_even, .z/.w = b0/b1 of nb_odd.
__device__ __align__(16) uint4 g_wh[36 * 4 * 32];

__global__ void prep_w(const float* __restrict__ w) {
    int idx = blockIdx.x * blockDim.x + threadIdx.x;
    if (idx >= 36 * 4 * 32) return;
    int lane = idx & 31;
    int j    = (idx >> 5) & 3;
    int kc16 = idx >> 7;
    int kl = kc16 >> 2, cq = kc16 & 3;
    int g = lane >> 2, t = lane & 3;
    int c0 = cq * 16 + 2 * t;
    int oce = (2 * j) * 8 + g;
    int oco = oce + 8;
    uint4 v;
    v.x = packh2(w[(oce * C_IN + c0)     * 9 + kl], w[(oce * C_IN + c0 + 1) * 9 + kl]);
    v.y = packh2(w[(oce * C_IN + c0 + 8) * 9 + kl], w[(oce * C_IN + c0 + 9) * 9 + kl]);
    v.z = packh2(w[(oco * C_IN + c0)     * 9 + kl], w[(oco * C_IN + c0 + 1) * 9 + kl]);
    v.w = packh2(w[(oco * C_IN + c0 + 8) * 9 + kl], w[(oco * C_IN + c0 + 9) * 9 + kl]);
    g_wh[idx] = v;
}

__global__ __launch_bounds__(NTHREADS, 3)
void depthconv_mma(const float* __restrict__ img,
                   const float* __restrict__ depth,
                   const float* __restrict__ bias,
                   float* __restrict__ out) {
    extern __shared__ char smem[];
    float* s_b    = (float*)(smem + OFF_BIAS);
    float* s_d    = (float*)(smem + OFF_D);
    float* s_dw   = (float*)(smem + OFF_DW);
    u32*   s_imgh = (u32*)  (smem + OFF_IMGH);   // [cpair(32)][pix(264)]

    const int tid  = threadIdx.x;
    const int lane = tid & 31;
    const int wid  = tid >> 5;          // 8 warps: each 16 M-pixels x 64 oc
    const int g    = lane >> 2;
    const int t    = lane & 3;
    const int pr   = wid >> 2;          // output row within p-pair
    const int qw   = (wid & 3) * 16;    // q base of this warp's 16-wide strip

    const int tIdx = blockIdx.x;
    const int b  = tIdx / TILES_PER_BATCH;
    const int r  = tIdx - b * TILES_PER_BATCH;
    const int p0 = (r >> 2) << 1;       // 0..252
    const int q0 = (r & 3) << 6;
    const int qcnt = min(64, W_OUT - q0);

    // ---- stage bias + depth halo (4 x 66) ----
    if (tid < C_OUT) s_b[tid] = bias[tid];
    for (int i = tid; i < 264; i += NTHREADS) {
        int rr = i / 66, cc = i - rr * 66;
        s_d[i] = depth[(size_t)b * H_IN * W_IN + (p0 + rr) * W_IN +
                       min(q0 + cc, W_IN - 1)];
    }
    // ---- stage img as fp16x2 channel pairs: s_imgh[cpair][pix] ----
    {
        const float* ip = img + (size_t)b * C_IN * H_IN * W_IN;
        for (int i = tid; i < 32 * PIXN; i += NTHREADS) {
            int cp  = i / PIXN;
            int pix = i - cp * PIXN;
            int rr  = pix / 66, cc = pix - rr * 66;
            size_t go = ((size_t)(2 * cp) * H_IN + (p0 + rr)) * W_IN +
                        min(q0 + cc, W_IN - 1);
            s_imgh[cp * PIXN + pix] = packh2(ip[go], ip[go + (size_t)H_IN * W_IN]);
        }
    }
    __syncthreads();
    // ---- dw[kl][m] (channel-independent) ----
    for (int i = tid; i < 1152; i += NTHREADS) {
        int kl = i >> 7, m = i & 127;
        int mpr = m >> 6, qq = m & 63;
        int k = kl / 3, l = kl - k * 3;
        float cen = s_d[(mpr + 1) * 66 + qq + 1];
        s_dw[i] = __expf(-ALPHA * fabsf(s_d[(mpr + k) * 66 + qq + l] - cen));
    }
    __syncthreads();

    float acc[8][4];
#pragma unroll
    for (int nb = 0; nb < 8; nb++)
#pragma unroll
        for (int rr = 0; rr < 4; rr++) acc[nb][rr] = 0.f;

    // ---- K loop: kl outer (not unrolled), cq inner x4 (16 channels each) ----
    const uint4* wlane = g_wh + lane;
    for (int k = 0; k < 3; k++) {
#pragma unroll 1
        for (int l = 0; l < 3; l++) {
            const int kl = k * 3 + l;
            const float* dwp = s_dw + kl * 128 + pr * 64 + qw;
            const u32 dwh0 = packh2(dwp[g],     dwp[g]);
            const u32 dwh1 = packh2(dwp[g + 8], dwp[g + 8]);
            const int pixbase = (pr + k) * 66 + l + qw;

#pragma unroll
            for (int cq = 0; cq < 4; cq++) {
                const uint4* wf = wlane + (size_t)(kl * 4 + cq) * 128;
                uint4 bq0 = __ldg(wf);
                uint4 bq1 = __ldg(wf + 32);
                uint4 bq2 = __ldg(wf + 64);
                uint4 bq3 = __ldg(wf + 96);

                const u32* pc  = s_imgh + (cq * 8 + t) * PIXN + pixbase;
                const u32* pc4 = pc + 4 * PIXN;    // channels +8

                u32 a0 = hmul2(pc [g],     dwh0);
                u32 a1 = hmul2(pc [g + 8], dwh1);
                u32 a2 = hmul2(pc4[g],     dwh0);
                u32 a3 = hmul2(pc4[g + 8], dwh1);

                MMA_F16(acc[0], a0, a1, a2, a3, bq0.x, bq0.y);
                MMA_F16(acc[1], a0, a1, a2, a3, bq0.z, bq0.w);
                MMA_F16(acc[2], a0, a1, a2, a3, bq1.x, bq1.y);
                MMA_F16(acc[3], a0, a1, a2, a3, bq1.z, bq1.w);
                MMA_F16(acc[4], a0, a1, a2, a3, bq2.x, bq2.y);
                MMA_F16(acc[5], a0, a1, a2, a3, bq2.z, bq2.w);
                MMA_F16(acc[6], a0, a1, a2, a3, bq3.x, bq3.y);
                MMA_F16(acc[7], a0, a1, a2, a3, bq3.z, bq3.w);
            }
        }
    }

    // ---- epilogue: bias + store ----
    // C frag: c0,c1 = (pix row g, oc 2t,2t+1); c2,c3 = (pix row g+8, same oc)
    const int qq0 = qw + g;
#pragma unroll
    for (int nb = 0; nb < 8; nb++) {
        const int oc = nb * 8 + t * 2;
        const float bs0 = s_b[oc], bs1 = s_b[oc + 1];
        const size_t base =
            (((size_t)b * C_OUT + oc) * H_OUT + (p0 + pr)) * W_OUT + q0;
        if (qq0 < qcnt) {
            out[base + qq0]                         = acc[nb][0] + bs0;
            out[base + (size_t)H_OUT * W_OUT + qq0] = acc[nb][1] + bs1;
        }
        if (qq0 + 8 < qcnt) {
            out[base + qq0 + 8]                         = acc[nb][2] + bs0;
            out[base + (size_t)H_OUT * W_OUT + qq0 + 8] = acc[nb][3] + bs1;
        }
    }
}

extern "C" void kernel_launch(void* const* d_in, const int* in_sizes, int n_in,
                              void* d_out, int out_size) {
    const float* img    = nullptr;
    const float* depth  = nullptr;
    const float* weight = nullptr;
    const float* bias   = nullptr;

    for (int i = 0; i < n_in; i++) {
        switch (in_sizes[i]) {
            case 4 * C_IN * H_IN * W_IN: img    = (const float*)d_in[i]; break;
            case 4 * 1 * H_IN * W_IN:    depth  = (const float*)d_in[i]; break;
            case C_OUT * C_IN * 9:       weight = (const float*)d_in[i]; break;
            case C_OUT:                  bias   = (const float*)d_in[i]; break;
            default: break;
        }
    }

    cudaFuncSetAttribute(depthconv_mma,
                         cudaFuncAttributeMaxDynamicSharedMemorySize, SMEM_TOTAL);

    prep_w<<<(36 * 4 * 32 + 255) / 256, 256>>>(weight);
    depthconv_mma<<<NTILES, NTHREADS, SMEM_TOTAL>>>(img, depth, bias, (float*)d_out);
}